// round 15
// baseline (speedup 1.0000x reference)
#include <cuda_runtime.h>
#include <cuda_fp16.h>
#include <cstdint>

#define ROWS   81920
#define NCOLS  4096
#define KG     48               // GEMM K: f1 level only (45 real + 3 pad)
#define ROWB   96               // g_Y row bytes (48 fp16)
#define HROWB  192              // g_Hh row bytes (96 fp16: f1|f2)
#define SSTR   112              // smem row stride (7 x 16B -> conflict-free ldmatrix)
#define TPC    8
#define MSLOTS 80
#define NT     32               // 4096 / 128 N-tiles

// SMEM: B tile 128x112 = 14336 ; A double buffer 2 x 14336
#define SM_B   0
#define SM_A0  14336
#define SM_A1  28672
#define SM_TOT 43008

__device__ __align__(16) __half        g_Y [(size_t)ROWS * KG];    // 7.9 MB (f1 signs)
__device__ __align__(16) __half        g_Hh[(size_t)NCOLS * 96];   // 786 KB: [n][f1(45)0(3)f2(45)0(3)]
__device__ unsigned long long          g_mask[ROWS];               // 45-bit sign masks
__device__ unsigned long long          g_p12[(size_t)ROWS * 64];   // per (row,ntile,wn): t1<<32|t2
__device__ int                         g_bbits;                    // max_col sum|f2| (float bits)

// ---------------- helpers ----------------
__device__ __forceinline__ uint32_t smem_u32(const void* p) {
    uint32_t a;
    asm("{ .reg .u64 t; cvta.to.shared.u64 t, %1; cvt.u32.u64 %0, t; }" : "=r"(a) : "l"(p));
    return a;
}
__device__ __forceinline__ void cpasync16(uint32_t dst, const void* src) {
    asm volatile("cp.async.cg.shared.global [%0], [%1], 16;" :: "r"(dst), "l"(src) : "memory");
}
#define CP_COMMIT() asm volatile("cp.async.commit_group;" ::: "memory")
#define CP_WAIT0()  asm volatile("cp.async.wait_group 0;" ::: "memory")

#define LDX4(d, addr)                                                              \
    asm volatile("ldmatrix.sync.aligned.m8n8.x4.shared.b16 {%0,%1,%2,%3}, [%4];"   \
        : "=r"((d)[0]), "=r"((d)[1]), "=r"((d)[2]), "=r"((d)[3]) : "r"(addr))

#define MMA(c, a, b0, b1)                                                          \
    asm volatile("mma.sync.aligned.m16n8k16.row.col.f32.f16.f16.f32 "              \
        "{%0,%1,%2,%3}, {%4,%5,%6,%7}, {%8,%9}, {%0,%1,%2,%3};"                    \
        : "+f"((c)[0]), "+f"((c)[1]), "+f"((c)[2]), "+f"((c)[3])                   \
        : "r"((a)[0]), "r"((a)[1]), "r"((a)[2]), "r"((a)[3]), "r"(b0), "r"(b1))

__device__ __forceinline__ unsigned pack_key(float v) {          // full monotone (refine only)
    unsigned u = __float_as_uint(v);
    return u ^ (unsigned)(((int)u >> 31) | 0x80000000);
}
__device__ __forceinline__ unsigned wmax32(unsigned v) {
#pragma unroll
    for (int off = 16; off > 0; off >>= 1)
        v = umax(v, __shfl_xor_sync(0xffffffffu, v, off));
    return v;
}
__device__ __forceinline__ unsigned long long wmax64(unsigned long long v) {
#pragma unroll
    for (int off = 16; off > 0; off >>= 1) {
        unsigned long long o = __shfl_xor_sync(0xffffffffu, v, off);
        if (o > v) v = o;
    }
    return v;
}
__device__ __forceinline__ float dec_u32key(unsigned k) {        // lower bound of score
    return __uint_as_float(k & 0xFFFFFF80u) - 512.f;
}

// ---------------------------------------------------------------------------
__global__ void k_zero() { g_bbits = 0; }

// ---------------------------------------------------------------------------
// K1: sign masks -> f1-level Y rows (fp16 ±1, 45 + 3 zeros) + save mask
// ---------------------------------------------------------------------------
__global__ void k_signs(const float* __restrict__ x,
                        const float* __restrict__ S,
                        const float* __restrict__ T)
{
    int i = blockIdx.x * blockDim.x + threadIdx.x;
    if (i >= ROWS) return;
    int token = i / 10, g = i % 10;
    const float* xr = x + (token >> 3) * 480 + (token & 7) * 60;

    unsigned long long mask = 0ull;
#pragma unroll
    for (int cl = 0; cl < 3; cl++) {
        int c = 3 * g + cl;
        float x0 = xr[c * 2 + 0], x1 = xr[c * 2 + 1];
        const float* S0 = S + c * 30;
        const float* S1 = S0 + 15;
        const float* Tc = T + c * 15;
#pragma unroll
        for (int k = 0; k < 15; k++) {
            float y = __fadd_rn(__fmul_rn(x0, S0[k]), __fmul_rn(x1, S1[k]));
            y = __fadd_rn(y, -Tc[k]);
            y = __fadd_rn(y, -1e-4f);
            if (y < 0.f) mask |= 1ull << (cl * 15 + k);
        }
    }
    g_mask[i] = mask;

    uint4* yp = reinterpret_cast<uint4*>(g_Y + (size_t)i * KG);
#pragma unroll
    for (int q = 0; q < 6; q++) {
        unsigned w[4];
#pragma unroll
        for (int e = 0; e < 4; e++) {
            int p0 = q * 8 + e * 2, p1 = p0 + 1;
            unsigned lo = (p0 < 45) ? (0x3C00u | ((unsigned)((mask >> p0) & 1ull) << 15)) : 0u;
            unsigned hi = (p1 < 45) ? (0x3C00u | ((unsigned)((mask >> p1) & 1ull) << 15)) : 0u;
            w[e] = lo | (hi << 16);
        }
        yp[q] = make_uint4(w[0], w[1], w[2], w[3]);
    }
}

// ---------------------------------------------------------------------------
// K2: exact 2-way fp16 split of H + per-col sum|f2| -> B_max
// ---------------------------------------------------------------------------
__global__ void k_hconv(const float* __restrict__ H)
{
    int n = blockIdx.x * blockDim.x + threadIdx.x;
    if (n >= NCOLS) return;
    __half* row = g_Hh + (size_t)n * 96;
    float bsum = 0.f;
    for (int d = 0; d < 45; d++) {
        float h = H[(size_t)d * NCOLS + n];
        __half f1 = __float2half_rn(h);
        float r1 = h - __half2float(f1);
        __half f2 = __float2half_rn(r1);
        row[d] = f1; row[48 + d] = f2;
        bsum += fabsf(__half2float(f2));
    }
    row[45] = row[46] = row[47] = __float2half_rn(0.f);
    row[93] = row[94] = row[95] = __float2half_rn(0.f);
    atomicMax(&g_bbits, (int)__float_as_uint(bsum));   // bsum >= 0: bits compare as ints
}

// ---------------------------------------------------------------------------
// K3: fp16 mma.sync GEMM, K=48, tree top-2 epilogue, direct gmem winners.
// grid 2560: ntile = bid & 31 (128 cols), mslot = bid >> 5.
// ---------------------------------------------------------------------------
__device__ __forceinline__ void load_A(uint32_t dst, int grow0, int tid)
{
    const char* src = (const char*)g_Y + (size_t)grow0 * ROWB;
#pragma unroll
    for (int it = 0; it < 3; it++) {
        int c = tid + it * 256;                  // 768 chunks: 128 rows x 6
        int r = c / 6, kc = c - r * 6;
        cpasync16(dst + (uint32_t)(r * SSTR + kc * 16), src + (size_t)r * ROWB + kc * 16);
    }
}

__global__ void __launch_bounds__(256, 2) k_gemm()
{
    extern __shared__ char smem[];
    uint32_t sb = smem_u32(smem);
    const int tid = threadIdx.x, wid = tid >> 5, lane = tid & 31;
    const int ntile = blockIdx.x & 31;
    const int mslot = blockIdx.x >> 5;
    const int wm = wid >> 1, wn = wid & 1;

    // B tile: 128 n-rows x 48 k (f1 only)
    {
        const char* hb = (const char*)g_Hh + (size_t)(ntile * 128) * HROWB;
#pragma unroll
        for (int it = 0; it < 3; it++) {
            int c = tid + it * 256;
            int r = c / 6, kc = c - r * 6;
            cpasync16(sb + SM_B + (uint32_t)(r * SSTR + kc * 16), hb + (size_t)r * HROWB + kc * 16);
        }
    }
    load_A(sb + SM_A0, mslot * TPC * 128, tid);
    CP_COMMIT();

    const int j = lane >> 3, lr = lane & 7;
    const uint32_t aoff = (uint32_t)((wm * 32 + (j & 1) * 8 + lr) * SSTR + (j >> 1) * 16);
    const uint32_t boff = sb + SM_B + (uint32_t)((wn * 64 + (j >> 1) * 8 + lr) * SSTR + (j & 1) * 16);
    const int lq = lane & 3, lrow = lane >> 2;
    const unsigned codeB = (unsigned)(127 - wn * 64 - 2 * lq);     // bits {0,3,4,5} all set

    for (int i = 0; i < TPC; i++) {
        const int b = i & 1;
        CP_WAIT0();
        __syncthreads();
        if (i < TPC - 1) {
            load_A(sb + (b ? SM_A0 : SM_A1), (mslot * TPC + i + 1) * 128, tid);
            CP_COMMIT();
        }

        const uint32_t abase = sb + (b ? SM_A1 : SM_A0) + aoff;
        float acc[2][8][4];
#pragma unroll
        for (int mb = 0; mb < 2; mb++)
#pragma unroll
            for (int nb = 0; nb < 8; nb++)
#pragma unroll
                for (int e = 0; e < 4; e++) acc[mb][nb][e] = 512.f;   // bias in init

#pragma unroll
        for (int ks = 0; ks < 3; ks++) {
            uint32_t a0[4], a1[4];
            LDX4(a0, abase + ks * 32);
            LDX4(a1, abase + ks * 32 + 16 * SSTR);
#pragma unroll
            for (int n16 = 0; n16 < 4; n16++) {
                uint32_t bb[4];
                LDX4(bb, boff + (uint32_t)(n16 * 16 * SSTR) + ks * 32);
                MMA(acc[0][2 * n16],     a0, bb[0], bb[1]);
                MMA(acc[1][2 * n16],     a1, bb[0], bb[1]);
                MMA(acc[0][2 * n16 + 1], a0, bb[2], bb[3]);
                MMA(acc[1][2 * n16 + 1], a1, bb[2], bb[3]);
            }
        }

        // Epilogue: tree top-2 over 16 keyed scores per (mb,h) row
        const int rowbase = (mslot * TPC + i) * 128 + wm * 32 + lrow;
#pragma unroll
        for (int mb = 0; mb < 2; mb++) {
#pragma unroll
            for (int h = 0; h < 2; h++) {
                unsigned hi[8], lo[8];
#pragma unroll
                for (int nb = 0; nb < 8; nb++) {
                    unsigned bt0 = __float_as_uint(acc[mb][nb][2 * h]);
                    unsigned bt1 = __float_as_uint(acc[mb][nb][2 * h + 1]);
                    unsigned k0 = ((bt0 & 0xFFFFFF80u) ^ codeB) ^ (unsigned)(8 * nb);
                    unsigned k1 = ((bt1 & 0xFFFFFF80u) ^ codeB) ^ (unsigned)(8 * nb + 1);
                    hi[nb] = umax(k0, k1);
                    lo[nb] = umin(k0, k1);
                }
#pragma unroll
                for (int s = 4; s >= 1; s >>= 1) {
#pragma unroll
                    for (int i2 = 0; i2 < s; i2++) {
                        unsigned m1 = umax(hi[i2], hi[i2 + s]);
                        unsigned m2 = umax(umin(hi[i2], hi[i2 + s]),
                                           umax(lo[i2], lo[i2 + s]));
                        hi[i2] = m1; lo[i2] = m2;
                    }
                }
                unsigned t1 = hi[0], t2 = lo[0];
#pragma unroll
                for (int off = 1; off < 4; off <<= 1) {
                    unsigned o1 = __shfl_xor_sync(0xffffffffu, t1, off);
                    unsigned o2 = __shfl_xor_sync(0xffffffffu, t2, off);
                    t2 = umax(umax(t2, o2), umin(t1, o1));
                    t1 = umax(t1, o1);
                }
                if (lq == 0)
                    g_p12[(size_t)(rowbase + mb * 16 + h * 8) * 64 + ntile * 2 + wn] =
                        ((unsigned long long)t1 << 32) | (unsigned long long)t2;
            }
        }
    }
}

// ---------------------------------------------------------------------------
// K4: certify-or-refine merge + LUT gather. One warp per row, 2 entries/lane.
// ---------------------------------------------------------------------------
__global__ void k_merge(const float* __restrict__ LUT, float2* __restrict__ out)
{
    __shared__ unsigned short cands[8][128];
    int wg    = (blockIdx.x * blockDim.x + threadIdx.x) >> 5;
    int lane  = threadIdx.x & 31;
    int wslot = (threadIdx.x >> 5) & 7;
    if (wg >= ROWS) return;

    const unsigned long long* p = g_p12 + (size_t)wg * 64;
    unsigned long long v0 = p[lane], v1 = p[lane + 32];
    unsigned a1 = (unsigned)(v0 >> 32), a2 = (unsigned)v0;
    unsigned b1 = (unsigned)(v1 >> 32), b2 = (unsigned)v1;

    unsigned M1 = wmax32(umax(a1, b1));
    unsigned c0 = (a1 == M1) ? a2 : a1;
    unsigned c1 = (b1 == M1) ? b2 : b1;
    unsigned M2 = wmax32(umax(c0, c1));

    // duplicate-key guard: top key must be unique or we must refine
    unsigned BA = __ballot_sync(0xffffffffu, a1 == M1);
    unsigned BB = __ballot_sync(0xffffffffu, b1 == M1);
    unsigned BC = __ballot_sync(0xffffffffu, a2 == M1);
    unsigned BD = __ballot_sync(0xffffffffu, b2 == M1);
    int n_top = __popc(BA) + __popc(BB) + __popc(BC) + __popc(BD);

    float val1 = dec_u32key(M1);
    float val2 = dec_u32key(M2);
    float thr  = 2.f * __uint_as_float((unsigned)g_bbits) + 0.03f;

    const float2* l2 = reinterpret_cast<const float2*>(LUT);
    int g = wg % 10;

    if (n_top == 1 && val1 - val2 > thr) {        // certified winner
        if (lane == 0) {
            int e   = BA ? (__ffs(BA) - 1) : (32 + __ffs(BB) - 1);
            int col = (e >> 1) * 128 + 127 - (int)(M1 & 0x7Fu);
            out[wg] = l2[(size_t)g * NCOLS + col];
        }
        return;
    }

    // Refine: rescore all candidate columns within the window exactly (f1+f2)
    float lim = val1 - thr;
    bool qa1 = dec_u32key(a1) >= lim, qb1 = dec_u32key(b1) >= lim;
    bool qa2 = dec_u32key(a2) >= lim, qb2 = dec_u32key(b2) >= lim;
    unsigned B0 = __ballot_sync(0xffffffffu, qa1);
    unsigned B1 = __ballot_sync(0xffffffffu, qb1);
    unsigned B2 = __ballot_sync(0xffffffffu, qa2);
    unsigned B3 = __ballot_sync(0xffffffffu, qb2);
    int o1 = __popc(B0), o2 = o1 + __popc(B1), o3 = o2 + __popc(B2);
    unsigned lm = (1u << lane) - 1u;
    if (qa1) cands[wslot][__popc(B0 & lm)]      = (unsigned short)(((lane) >> 1) * 128 + 127 - (int)(a1 & 0x7Fu) + ((lane & 1) ? 0 : 0));
    // NOTE: entry index e = lane for (a*), e = lane+32 for (b*); col = (e>>1)*128 + 127-(key&0x7F)
    if (qa1) cands[wslot][__popc(B0 & lm)]      = (unsigned short)((lane >> 1) * 128 + ((lane & 1) ? 0 : 0) + 127 - (int)(a1 & 0x7Fu));
    if (qb1) cands[wslot][o1 + __popc(B1 & lm)] = (unsigned short)(((lane + 32) >> 1) * 128 + 127 - (int)(b1 & 0x7Fu));
    if (qa2) cands[wslot][o2 + __popc(B2 & lm)] = (unsigned short)((lane >> 1) * 128 + 127 - (int)(a2 & 0x7Fu));
    if (qb2) cands[wslot][o3 + __popc(B3 & lm)] = (unsigned short)(((lane + 32) >> 1) * 128 + 127 - (int)(b2 & 0x7Fu));
    int nc = o3 + __popc(B3);
    __syncwarp();

    unsigned long long mask = g_mask[wg];
    unsigned long long best = 0;
    for (int k = lane; k < nc; k += 32) {
        int col = cands[wslot][k];
        const __half* hr = g_Hh + (size_t)col * 96;
        float s = 0.f;
#pragma unroll
        for (int d = 0; d < 45; d++) {
            float sgn = ((mask >> d) & 1ull) ? -1.f : 1.f;
            s += sgn * (__half2float(hr[d]) + __half2float(hr[48 + d]));
        }
        unsigned long long pk = ((unsigned long long)pack_key(s) << 32)
                              | (unsigned long long)(4095u - (unsigned)col);
        if (pk > best) best = pk;
    }
    best = wmax64(best);
    if (lane == 0) {
        int col = 4095 - (int)(unsigned)best;
        out[wg] = l2[(size_t)g * NCOLS + col];
    }
}

// ---------------------------------------------------------------------------
extern "C" void kernel_launch(void* const* d_in, const int* in_sizes, int n_in,
                              void* d_out, int out_size)
{
    const float* x   = (const float*)d_in[0];
    const float* S   = (const float*)d_in[1];
    const float* T   = (const float*)d_in[2];
    const float* H   = (const float*)d_in[3];
    const float* LUT = (const float*)d_in[4];
    (void)in_sizes; (void)n_in; (void)out_size;

    cudaFuncSetAttribute(k_gemm, cudaFuncAttributeMaxDynamicSharedMemorySize, SM_TOT);

    k_zero <<<1, 1>>>();
    k_signs<<<(ROWS + 255) / 256, 256>>>(x, S, T);
    k_hconv<<<NCOLS / 256, 256>>>(H);
    k_gemm <<<MSLOTS * NT, 256, SM_TOT>>>();
    k_merge<<<(ROWS * 32 + 255) / 256, 256>>>(LUT, (float2*)d_out);
}

// round 16
// speedup vs baseline: 1.0152x; 1.0152x over previous
#include <cuda_runtime.h>
#include <cuda_fp16.h>
#include <cstdint>

#define ROWS   81920
#define NCOLS  4096
#define KG     48               // GEMM K: f1 level only (45 real + 3 pad)
#define ROWB   96               // g_Y row bytes (48 fp16)
#define HROWB  192              // g_Hh row bytes (96 fp16: f1|f2)
#define SSTR   112              // smem row stride (7 x 16B -> conflict-free ldmatrix)
#define TPC    16               // M-tiles (of 64 rows) per CTA
#define MSLOTS 80
#define NT     32               // 4096 / 128 N-tiles

// SMEM: B tile 128x112 = 14336 ; A double buffer 2 x (64x112 = 7168)
#define SM_B   0
#define SM_A0  14336
#define SM_A1  21504
#define SM_TOT 28672

__device__ __align__(16) __half        g_Y [(size_t)ROWS * KG];    // 7.9 MB (f1 signs)
__device__ __align__(16) __half        g_Hh[(size_t)NCOLS * 96];   // 786 KB: [n][f1(45)0(3)f2(45)0(3)]
__device__ unsigned long long          g_mask[ROWS];               // 45-bit sign masks
__device__ unsigned long long          g_p12[(size_t)ROWS * NT];   // per (row,ntile): top1<<32 | top2
__device__ int                         g_bbits;                    // max_col sum|f2| (float bits)

// ---------------- helpers ----------------
__device__ __forceinline__ uint32_t smem_u32(const void* p) {
    uint32_t a;
    asm("{ .reg .u64 t; cvta.to.shared.u64 t, %1; cvt.u32.u64 %0, t; }" : "=r"(a) : "l"(p));
    return a;
}
__device__ __forceinline__ void cpasync16(uint32_t dst, const void* src) {
    asm volatile("cp.async.cg.shared.global [%0], [%1], 16;" :: "r"(dst), "l"(src) : "memory");
}
#define CP_COMMIT() asm volatile("cp.async.commit_group;" ::: "memory")
#define CP_WAIT0()  asm volatile("cp.async.wait_group 0;" ::: "memory")

#define LDX4(d, addr)                                                              \
    asm volatile("ldmatrix.sync.aligned.m8n8.x4.shared.b16 {%0,%1,%2,%3}, [%4];"   \
        : "=r"((d)[0]), "=r"((d)[1]), "=r"((d)[2]), "=r"((d)[3]) : "r"(addr))

#define MMA(c, a, b0, b1)                                                          \
    asm volatile("mma.sync.aligned.m16n8k16.row.col.f32.f16.f16.f32 "              \
        "{%0,%1,%2,%3}, {%4,%5,%6,%7}, {%8,%9}, {%0,%1,%2,%3};"                    \
        : "+f"((c)[0]), "+f"((c)[1]), "+f"((c)[2]), "+f"((c)[3])                   \
        : "r"((a)[0]), "r"((a)[1]), "r"((a)[2]), "r"((a)[3]), "r"(b0), "r"(b1))

__device__ __forceinline__ unsigned pack_key(float v) {          // full monotone (refine only)
    unsigned u = __float_as_uint(v);
    return u ^ (unsigned)(((int)u >> 31) | 0x80000000);
}
__device__ __forceinline__ unsigned wmax32(unsigned v) {
#pragma unroll
    for (int off = 16; off > 0; off >>= 1)
        v = umax(v, __shfl_xor_sync(0xffffffffu, v, off));
    return v;
}
__device__ __forceinline__ unsigned long long wmax64(unsigned long long v) {
#pragma unroll
    for (int off = 16; off > 0; off >>= 1) {
        unsigned long long o = __shfl_xor_sync(0xffffffffu, v, off);
        if (o > v) v = o;
    }
    return v;
}
__device__ __forceinline__ float dec_u32key(unsigned k) {        // lower bound of score
    return __uint_as_float(k & 0xFFFFFF80u) - 512.f;
}

// ---------------------------------------------------------------------------
__global__ void k_zero() { g_bbits = 0; }

// ---------------------------------------------------------------------------
// K1: sign masks -> f1-level Y rows (fp16 ±1, 45 + 3 zeros) + save mask
// ---------------------------------------------------------------------------
__global__ void k_signs(const float* __restrict__ x,
                        const float* __restrict__ S,
                        const float* __restrict__ T)
{
    int i = blockIdx.x * blockDim.x + threadIdx.x;
    if (i >= ROWS) return;
    int token = i / 10, g = i % 10;
    const float* xr = x + (token >> 3) * 480 + (token & 7) * 60;

    unsigned long long mask = 0ull;
#pragma unroll
    for (int cl = 0; cl < 3; cl++) {
        int c = 3 * g + cl;
        float x0 = xr[c * 2 + 0], x1 = xr[c * 2 + 1];
        const float* S0 = S + c * 30;
        const float* S1 = S0 + 15;
        const float* Tc = T + c * 15;
#pragma unroll
        for (int k = 0; k < 15; k++) {
            float y = __fadd_rn(__fmul_rn(x0, S0[k]), __fmul_rn(x1, S1[k]));
            y = __fadd_rn(y, -Tc[k]);
            y = __fadd_rn(y, -1e-4f);
            if (y < 0.f) mask |= 1ull << (cl * 15 + k);
        }
    }
    g_mask[i] = mask;

    uint4* yp = reinterpret_cast<uint4*>(g_Y + (size_t)i * KG);
#pragma unroll
    for (int q = 0; q < 6; q++) {
        unsigned w[4];
#pragma unroll
        for (int e = 0; e < 4; e++) {
            int p0 = q * 8 + e * 2, p1 = p0 + 1;
            unsigned lo = (p0 < 45) ? (0x3C00u | ((unsigned)((mask >> p0) & 1ull) << 15)) : 0u;
            unsigned hi = (p1 < 45) ? (0x3C00u | ((unsigned)((mask >> p1) & 1ull) << 15)) : 0u;
            w[e] = lo | (hi << 16);
        }
        yp[q] = make_uint4(w[0], w[1], w[2], w[3]);
    }
}

// ---------------------------------------------------------------------------
// K2: exact 2-way fp16 split of H + per-col sum|f2| -> B_max
// ---------------------------------------------------------------------------
__global__ void k_hconv(const float* __restrict__ H)
{
    int n = blockIdx.x * blockDim.x + threadIdx.x;
    if (n >= NCOLS) return;
    __half* row = g_Hh + (size_t)n * 96;
    float bsum = 0.f;
    for (int d = 0; d < 45; d++) {
        float h = H[(size_t)d * NCOLS + n];
        __half f1 = __float2half_rn(h);
        float r1 = h - __half2float(f1);
        __half f2 = __float2half_rn(r1);
        row[d] = f1; row[48 + d] = f2;
        bsum += fabsf(__half2float(f2));
    }
    row[45] = row[46] = row[47] = __float2half_rn(0.f);
    row[93] = row[94] = row[95] = __float2half_rn(0.f);
    atomicMax(&g_bbits, (int)__float_as_uint(bsum));   // bsum >= 0: bits compare as ints
}

// ---------------------------------------------------------------------------
// K3: fp16 mma.sync GEMM, K=48, CTA tile M64xN128, warp tile 32x32.
// 3 CTAs/SM (occupancy fix). grid 2560: ntile = bid & 31, mslot = bid >> 5.
// ---------------------------------------------------------------------------
__device__ __forceinline__ void load_A(uint32_t dst, int grow0, int tid)
{
    const char* src = (const char*)g_Y + (size_t)grow0 * ROWB;
#pragma unroll
    for (int it = 0; it < 2; it++) {
        int c = tid + it * 256;                  // 384 chunks: 64 rows x 6
        if (c < 384) {
            int r = c / 6, kc = c - r * 6;
            cpasync16(dst + (uint32_t)(r * SSTR + kc * 16), src + (size_t)r * ROWB + kc * 16);
        }
    }
}

__global__ void __launch_bounds__(256, 3) k_gemm()
{
    extern __shared__ char smem[];
    __shared__ unsigned win1[64][4], win2[64][4];
    uint32_t sb = smem_u32(smem);
    const int tid = threadIdx.x, wid = tid >> 5, lane = tid & 31;
    const int ntile = blockIdx.x & 31;
    const int mslot = blockIdx.x >> 5;
    const int wm = wid >> 2, wn = wid & 3;       // warp grid 2(m) x 4(n)

    // B tile: 128 n-rows x 48 k (f1 only)
    {
        const char* hb = (const char*)g_Hh + (size_t)(ntile * 128) * HROWB;
#pragma unroll
        for (int it = 0; it < 3; it++) {
            int c = tid + it * 256;
            int r = c / 6, kc = c - r * 6;
            cpasync16(sb + SM_B + (uint32_t)(r * SSTR + kc * 16), hb + (size_t)r * HROWB + kc * 16);
        }
    }
    load_A(sb + SM_A0, mslot * TPC * 64, tid);
    CP_COMMIT();

    const int j = lane >> 3, lr = lane & 7;
    const uint32_t aoff = (uint32_t)((wm * 32 + (j & 1) * 8 + lr) * SSTR + (j >> 1) * 16);
    const uint32_t boff = sb + SM_B + (uint32_t)((wn * 32 + (j >> 1) * 8 + lr) * SSTR + (j & 1) * 16);
    const int lq = lane & 3, lrow = lane >> 2;
    const unsigned codeB = (unsigned)(127 - wn * 32 - 2 * lq);     // bits {0,3,4} always set

    for (int i = 0; i < TPC; i++) {
        const int b = i & 1;
        CP_WAIT0();
        __syncthreads();
        if (i < TPC - 1) {
            load_A(sb + (b ? SM_A0 : SM_A1), (mslot * TPC + i + 1) * 64, tid);
            CP_COMMIT();
        }

        const uint32_t abase = sb + (b ? SM_A1 : SM_A0) + aoff;
        float acc[2][4][4];
#pragma unroll
        for (int mb = 0; mb < 2; mb++)
#pragma unroll
            for (int nb = 0; nb < 4; nb++)
#pragma unroll
                for (int e = 0; e < 4; e++) acc[mb][nb][e] = 512.f;   // bias in init

#pragma unroll
        for (int ks = 0; ks < 3; ks++) {
            uint32_t a0[4], a1[4], bb0[4], bb1[4];
            LDX4(a0, abase + ks * 32);
            LDX4(a1, abase + ks * 32 + 16 * SSTR);
            LDX4(bb0, boff + ks * 32);
            LDX4(bb1, boff + ks * 32 + 16 * SSTR);
            MMA(acc[0][0], a0, bb0[0], bb0[1]);
            MMA(acc[1][0], a1, bb0[0], bb0[1]);
            MMA(acc[0][1], a0, bb0[2], bb0[3]);
            MMA(acc[1][1], a1, bb0[2], bb0[3]);
            MMA(acc[0][2], a0, bb1[0], bb1[1]);
            MMA(acc[1][2], a1, bb1[0], bb1[1]);
            MMA(acc[0][3], a0, bb1[2], bb1[3]);
            MMA(acc[1][3], a1, bb1[2], bb1[3]);
        }

        // Epilogue: u32-key top-2 per (mb,h) row over this warp's 32 columns
#pragma unroll
        for (int mb = 0; mb < 2; mb++) {
#pragma unroll
            for (int h = 0; h < 2; h++) {
                unsigned t1 = 0, t2 = 0;
#pragma unroll
                for (int nb = 0; nb < 4; nb++) {
#pragma unroll
                    for (int t = 0; t < 2; t++) {
                        unsigned bits = __float_as_uint(acc[mb][nb][2 * h + t]);
                        unsigned key  = ((bits & 0xFFFFFF80u) ^ codeB) ^ (unsigned)(8 * nb + t);
                        unsigned n1 = umax(t1, key);
                        t2 = umax(t2, umin(t1, key));
                        t1 = n1;
                    }
                }
#pragma unroll
                for (int off = 1; off < 4; off <<= 1) {
                    unsigned o1 = __shfl_xor_sync(0xffffffffu, t1, off);
                    unsigned o2 = __shfl_xor_sync(0xffffffffu, t2, off);
                    t2 = umax(umax(t2, o2), umin(t1, o1));
                    t1 = umax(t1, o1);
                }
                if (lq == 0) {
                    int rl = wm * 32 + mb * 16 + h * 8 + lrow;     // 0..63
                    win1[rl][wn] = t1; win2[rl][wn] = t2;
                }
            }
        }
        __syncthreads();
        if (tid < 64) {
            unsigned h0 = win1[tid][0], l0 = win2[tid][0];
            unsigned h1 = win1[tid][1], l1 = win2[tid][1];
            unsigned h2 = win1[tid][2], l2 = win2[tid][2];
            unsigned h3 = win1[tid][3], l3 = win2[tid][3];
            unsigned pA = umax(h0, h1), sA = umax(umin(h0, h1), umax(l0, l1));
            unsigned pB = umax(h2, h3), sB = umax(umin(h2, h3), umax(l2, l3));
            unsigned T1 = umax(pA, pB);
            unsigned T2 = umax(umin(pA, pB), umax(sA, sB));
            g_p12[(size_t)((mslot * TPC + i) * 64 + tid) * NT + ntile] =
                ((unsigned long long)T1 << 32) | (unsigned long long)T2;
        }
    }
}

// ---------------------------------------------------------------------------
// K4: certify-or-refine merge + LUT gather. One warp per row (lane = ntile).
// ---------------------------------------------------------------------------
__global__ void k_merge(const float* __restrict__ LUT, float2* __restrict__ out)
{
    __shared__ unsigned short cands[8][64];
    int wg    = (blockIdx.x * blockDim.x + threadIdx.x) >> 5;
    int lane  = threadIdx.x & 31;
    int wslot = (threadIdx.x >> 5) & 7;
    if (wg >= ROWS) return;

    unsigned long long v = g_p12[(size_t)wg * NT + lane];
    unsigned t1 = (unsigned)(v >> 32), t2 = (unsigned)v;

    unsigned M1 = wmax32(t1);
    unsigned M2 = wmax32((t1 == M1) ? t2 : t1);   // covers global #2

    // duplicate-key guard: top key must be unique across all stored keys
    unsigned B1g = __ballot_sync(0xffffffffu, t1 == M1);
    unsigned B2g = __ballot_sync(0xffffffffu, t2 == M1);
    int n_top = __popc(B1g) + __popc(B2g);

    float val1 = dec_u32key(M1);
    float val2 = dec_u32key(M2);
    float thr  = 2.f * __uint_as_float((unsigned)g_bbits) + 0.03f;

    const float2* l2 = reinterpret_cast<const float2*>(LUT);
    int g = wg % 10;

    if (n_top == 1 && val1 - val2 > thr) {        // certified winner
        if (lane == 0) {
            int wl  = __ffs(B1g) - 1;
            int col = wl * 128 + 127 - (int)(M1 & 0x7Fu);
            out[wg] = l2[(size_t)g * NCOLS + col];
        }
        return;
    }

    // Refine: rescore all candidate columns within the window exactly (f1+f2)
    float lim = val1 - thr;
    bool q1 = dec_u32key(t1) >= lim;
    bool q2 = dec_u32key(t2) >= lim;
    unsigned b1 = __ballot_sync(0xffffffffu, q1);
    unsigned b2 = __ballot_sync(0xffffffffu, q2);
    int n1 = __popc(b1);
    unsigned lmask = (1u << lane) - 1u;
    if (q1) cands[wslot][__popc(b1 & lmask)]      = (unsigned short)(lane * 128 + 127 - (int)(t1 & 0x7Fu));
    if (q2) cands[wslot][n1 + __popc(b2 & lmask)] = (unsigned short)(lane * 128 + 127 - (int)(t2 & 0x7Fu));
    int nc = n1 + __popc(b2);
    __syncwarp();

    unsigned long long mask = g_mask[wg];
    unsigned long long best = 0;
    for (int k = lane; k < nc; k += 32) {
        int col = cands[wslot][k];
        const __half* hr = g_Hh + (size_t)col * 96;
        float s = 0.f;
#pragma unroll
        for (int d = 0; d < 45; d++) {
            float sgn = ((mask >> d) & 1ull) ? -1.f : 1.f;
            s += sgn * (__half2float(hr[d]) + __half2float(hr[48 + d]));
        }
        unsigned long long pk = ((unsigned long long)pack_key(s) << 32)
                              | (unsigned long long)(4095u - (unsigned)col);
        if (pk > best) best = pk;
    }
    best = wmax64(best);
    if (lane == 0) {
        int col = 4095 - (int)(unsigned)best;
        out[wg] = l2[(size_t)g * NCOLS + col];
    }
}

// ---------------------------------------------------------------------------
extern "C" void kernel_launch(void* const* d_in, const int* in_sizes, int n_in,
                              void* d_out, int out_size)
{
    const float* x   = (const float*)d_in[0];
    const float* S   = (const float*)d_in[1];
    const float* T   = (const float*)d_in[2];
    const float* H   = (const float*)d_in[3];
    const float* LUT = (const float*)d_in[4];
    (void)in_sizes; (void)n_in; (void)out_size;

    cudaFuncSetAttribute(k_gemm, cudaFuncAttributeMaxDynamicSharedMemorySize, SM_TOT);

    k_zero <<<1, 1>>>();
    k_signs<<<(ROWS + 255) / 256, 256>>>(x, S, T);
    k_hconv<<<NCOLS / 256, 256>>>(H);
    k_gemm <<<MSLOTS * NT, 256, SM_TOT>>>();
    k_merge<<<(ROWS * 32 + 255) / 256, 256>>>(LUT, (float2*)d_out);
}

// round 17
// speedup vs baseline: 1.0511x; 1.0353x over previous
#include <cuda_runtime.h>
#include <cuda_fp16.h>
#include <cstdint>

#define ROWS   81920
#define NCOLS  4096
#define KG     48               // GEMM K: f1 level only (45 real + 3 pad)
#define ROWB   96               // g_Y row bytes (48 fp16)
#define HROWB  192              // g_Hh row bytes (96 fp16: f1|f2)
#define SSTR   112              // smem row stride (7 x 16B -> conflict-free ldmatrix)
#define TPC    8
#define MSLOTS 80
#define NT     32               // 4096 / 128 N-tiles

// SMEM: B tile 128x112 = 14336 ; A double buffer 2 x 14336
#define SM_B   0
#define SM_A0  14336
#define SM_A1  28672
#define SM_TOT 43008

__device__ __align__(16) __half        g_Y [(size_t)ROWS * KG];    // 7.9 MB (f1 signs)
__device__ __align__(16) __half        g_Hh[(size_t)NCOLS * 96];   // 786 KB: [n][f1(45)0(3)f2(45)0(3)]
__device__ unsigned long long          g_mask[ROWS];               // 45-bit sign masks
__device__ unsigned long long          g_p12[(size_t)ROWS * NT];   // per (row,ntile): top1<<32 | top2 (pair keys)
__device__ int                         g_bbits;                    // max_col sum|f2| (float bits; monotone across replays)

// ---------------- helpers ----------------
__device__ __forceinline__ uint32_t smem_u32(const void* p) {
    uint32_t a;
    asm("{ .reg .u64 t; cvta.to.shared.u64 t, %1; cvt.u32.u64 %0, t; }" : "=r"(a) : "l"(p));
    return a;
}
__device__ __forceinline__ void cpasync16(uint32_t dst, const void* src) {
    asm volatile("cp.async.cg.shared.global [%0], [%1], 16;" :: "r"(dst), "l"(src) : "memory");
}
#define CP_COMMIT() asm volatile("cp.async.commit_group;" ::: "memory")
#define CP_WAIT0()  asm volatile("cp.async.wait_group 0;" ::: "memory")

#define LDX4(d, addr)                                                              \
    asm volatile("ldmatrix.sync.aligned.m8n8.x4.shared.b16 {%0,%1,%2,%3}, [%4];"   \
        : "=r"((d)[0]), "=r"((d)[1]), "=r"((d)[2]), "=r"((d)[3]) : "r"(addr))

#define MMA(c, a, b0, b1)                                                          \
    asm volatile("mma.sync.aligned.m16n8k16.row.col.f32.f16.f16.f32 "              \
        "{%0,%1,%2,%3}, {%4,%5,%6,%7}, {%8,%9}, {%0,%1,%2,%3};"                    \
        : "+f"((c)[0]), "+f"((c)[1]), "+f"((c)[2]), "+f"((c)[3])                   \
        : "r"((a)[0]), "r"((a)[1]), "r"((a)[2]), "r"((a)[3]), "r"(b0), "r"(b1))

__device__ __forceinline__ unsigned pack_key(float v) {          // full monotone (refine)
    unsigned u = __float_as_uint(v);
    return u ^ (unsigned)(((int)u >> 31) | 0x80000000);
}
__device__ __forceinline__ unsigned wmax32(unsigned v) {
#pragma unroll
    for (int off = 16; off > 0; off >>= 1)
        v = umax(v, __shfl_xor_sync(0xffffffffu, v, off));
    return v;
}
__device__ __forceinline__ unsigned long long wmax64(unsigned long long v) {
#pragma unroll
    for (int off = 16; off > 0; off >>= 1) {
        unsigned long long o = __shfl_xor_sync(0xffffffffu, v, off);
        if (o > v) v = o;
    }
    return v;
}
__device__ __forceinline__ float dec_key(unsigned k) {           // lower bound of pair max
    return __uint_as_float(k & 0xFFFFFFC0u) - 512.f;
}

// ---------------------------------------------------------------------------
// K1 (fused): blocks [0,320) -> sign masks + f1 Y rows; blocks [320,336) ->
// exact 2-way fp16 split of H + per-col sum|f2| -> B_max (atomicMax is
// idempotent across graph replays; g_bbits static-zero before first run).
// ---------------------------------------------------------------------------
__global__ void k_prep(const float* __restrict__ x,
                       const float* __restrict__ S,
                       const float* __restrict__ T,
                       const float* __restrict__ H)
{
    if (blockIdx.x >= 320) {                     // H conversion
        int n = (blockIdx.x - 320) * 256 + threadIdx.x;
        if (n >= NCOLS) return;
        __half* row = g_Hh + (size_t)n * 96;
        float bsum = 0.f;
        for (int d = 0; d < 45; d++) {
            float h = H[(size_t)d * NCOLS + n];
            __half f1 = __float2half_rn(h);
            float r1 = h - __half2float(f1);
            __half f2 = __float2half_rn(r1);
            row[d] = f1; row[48 + d] = f2;
            bsum += fabsf(__half2float(f2));
        }
        row[45] = row[46] = row[47] = __float2half_rn(0.f);
        row[93] = row[94] = row[95] = __float2half_rn(0.f);
        atomicMax(&g_bbits, (int)__float_as_uint(bsum));
        return;
    }

    int i = blockIdx.x * blockDim.x + threadIdx.x;
    if (i >= ROWS) return;
    int token = i / 10, g = i % 10;
    const float* xr = x + (token >> 3) * 480 + (token & 7) * 60;

    unsigned long long mask = 0ull;
#pragma unroll
    for (int cl = 0; cl < 3; cl++) {
        int c = 3 * g + cl;
        float x0 = xr[c * 2 + 0], x1 = xr[c * 2 + 1];
        const float* S0 = S + c * 30;
        const float* S1 = S0 + 15;
        const float* Tc = T + c * 15;
#pragma unroll
        for (int k = 0; k < 15; k++) {
            float y = __fadd_rn(__fmul_rn(x0, S0[k]), __fmul_rn(x1, S1[k]));
            y = __fadd_rn(y, -Tc[k]);
            y = __fadd_rn(y, -1e-4f);
            if (y < 0.f) mask |= 1ull << (cl * 15 + k);
        }
    }
    g_mask[i] = mask;

    uint4* yp = reinterpret_cast<uint4*>(g_Y + (size_t)i * KG);
#pragma unroll
    for (int q = 0; q < 6; q++) {
        unsigned w[4];
#pragma unroll
        for (int e = 0; e < 4; e++) {
            int p0 = q * 8 + e * 2, p1 = p0 + 1;
            unsigned lo = (p0 < 45) ? (0x3C00u | ((unsigned)((mask >> p0) & 1ull) << 15)) : 0u;
            unsigned hi = (p1 < 45) ? (0x3C00u | ((unsigned)((mask >> p1) & 1ull) << 15)) : 0u;
            w[e] = lo | (hi << 16);
        }
        yp[q] = make_uint4(w[0], w[1], w[2], w[3]);
    }
}

// ---------------------------------------------------------------------------
// K2: fp16 mma.sync GEMM, K=48, pair-max top-2 epilogue (2.5 alu ops/score).
// grid 2560: ntile = bid & 31 (128 cols), mslot = bid >> 5. 2 CTAs/SM.
// Keys select over column PAIRS: key = (pairmax_bits & ~0x3F) ^ paircode.
// ---------------------------------------------------------------------------
__device__ __forceinline__ void load_A(uint32_t dst, int grow0, int tid)
{
    const char* src = (const char*)g_Y + (size_t)grow0 * ROWB;
#pragma unroll
    for (int it = 0; it < 3; it++) {
        int c = tid + it * 256;                  // 768 chunks: 128 rows x 6
        int r = c / 6, kc = c - r * 6;
        cpasync16(dst + (uint32_t)(r * SSTR + kc * 16), src + (size_t)r * ROWB + kc * 16);
    }
}

__global__ void __launch_bounds__(256, 2) k_gemm()
{
    extern __shared__ char smem[];
    __shared__ unsigned win1[128][2], win2[128][2];
    uint32_t sb = smem_u32(smem);
    const int tid = threadIdx.x, wid = tid >> 5, lane = tid & 31;
    const int ntile = blockIdx.x & 31;
    const int mslot = blockIdx.x >> 5;
    const int wm = wid >> 1, wn = wid & 1;

    // B tile: 128 n-rows x 48 k (f1 only)
    {
        const char* hb = (const char*)g_Hh + (size_t)(ntile * 128) * HROWB;
#pragma unroll
        for (int it = 0; it < 3; it++) {
            int c = tid + it * 256;
            int r = c / 6, kc = c - r * 6;
            cpasync16(sb + SM_B + (uint32_t)(r * SSTR + kc * 16), hb + (size_t)r * HROWB + kc * 16);
        }
    }
    load_A(sb + SM_A0, mslot * TPC * 128, tid);
    CP_COMMIT();

    const int j = lane >> 3, lr = lane & 7;
    const uint32_t aoff = (uint32_t)((wm * 32 + (j & 1) * 8 + lr) * SSTR + (j >> 1) * 16);
    const uint32_t boff = sb + SM_B + (uint32_t)((wn * 64 + (j >> 1) * 8 + lr) * SSTR + (j & 1) * 16);
    const int lq = lane & 3, lrow = lane >> 2;
    // pair code: pair_local = wn*32 + nb*4 + lq (6 bits); code = 63 - pair_local
    // base (63 - wn*32 - lq) has bits {2,3,4} set -> XOR with nb<<2 is exact subtract
    const unsigned codeP = (unsigned)(63 - wn * 32 - lq);

    for (int i = 0; i < TPC; i++) {
        const int b = i & 1;
        CP_WAIT0();
        __syncthreads();
        if (i < TPC - 1) {
            load_A(sb + (b ? SM_A0 : SM_A1), (mslot * TPC + i + 1) * 128, tid);
            CP_COMMIT();
        }

        const uint32_t abase = sb + (b ? SM_A1 : SM_A0) + aoff;
        float acc[2][8][4];
#pragma unroll
        for (int mb = 0; mb < 2; mb++)
#pragma unroll
            for (int nb = 0; nb < 8; nb++)
#pragma unroll
                for (int e = 0; e < 4; e++) acc[mb][nb][e] = 512.f;   // bias: bits monotone

#pragma unroll
        for (int ks = 0; ks < 3; ks++) {
            uint32_t a0[4], a1[4];
            LDX4(a0, abase + ks * 32);
            LDX4(a1, abase + ks * 32 + 16 * SSTR);
#pragma unroll
            for (int n16 = 0; n16 < 4; n16++) {
                uint32_t bb[4];
                LDX4(bb, boff + (uint32_t)(n16 * 16 * SSTR) + ks * 32);
                MMA(acc[0][2 * n16],     a0, bb[0], bb[1]);
                MMA(acc[1][2 * n16],     a1, bb[0], bb[1]);
                MMA(acc[0][2 * n16 + 1], a0, bb[2], bb[3]);
                MMA(acc[1][2 * n16 + 1], a1, bb[2], bb[3]);
            }
        }

        // Epilogue: pair-max on raw bits (no key), then keyed top-2 over 8 pairs
#pragma unroll
        for (int mb = 0; mb < 2; mb++) {
#pragma unroll
            for (int h = 0; h < 2; h++) {
                unsigned t1 = 0, t2 = 0;
#pragma unroll
                for (int nb = 0; nb < 8; nb++) {
                    unsigned b0 = __float_as_uint(acc[mb][nb][2 * h]);
                    unsigned b1 = __float_as_uint(acc[mb][nb][2 * h + 1]);
                    unsigned pm = umax(b0, b1);                       // positive floats
                    unsigned key = (pm & 0xFFFFFFC0u) ^ (codeP ^ (unsigned)(nb << 2));
                    unsigned n1 = umax(t1, key);
                    t2 = umax(t2, umin(t1, key));
                    t1 = n1;
                }
#pragma unroll
                for (int off = 1; off < 4; off <<= 1) {
                    unsigned o1 = __shfl_xor_sync(0xffffffffu, t1, off);
                    unsigned o2 = __shfl_xor_sync(0xffffffffu, t2, off);
                    t2 = umax(umax(t2, o2), umin(t1, o1));
                    t1 = umax(t1, o1);
                }
                if (lq == 0) {
                    int rl = wm * 32 + mb * 16 + h * 8 + lrow;
                    win1[rl][wn] = t1; win2[rl][wn] = t2;
                }
            }
        }
        __syncthreads();
        if (tid < 128) {
            unsigned a1 = win1[tid][0], a2 = win2[tid][0];
            unsigned b1 = win1[tid][1], b2 = win2[tid][1];
            unsigned T1 = umax(a1, b1);
            unsigned T2 = umax(umin(a1, b1), umax(a2, b2));
            g_p12[(size_t)((mslot * TPC + i) * 128 + tid) * NT + ntile] =
                ((unsigned long long)T1 << 32) | (unsigned long long)T2;
        }
    }
}

// ---------------------------------------------------------------------------
// K3: window-refine merge + LUT gather. One warp per row (lane = ntile).
// All pairs within thr of the best pair-key get BOTH columns rescored exactly
// (covers the pair-partner runner-up the per-tile top-2 can miss).
// ---------------------------------------------------------------------------
__global__ void k_merge(const float* __restrict__ LUT, float2* __restrict__ out)
{
    __shared__ unsigned short cands[8][64];      // global pair indices (0..2047)
    int wg    = (blockIdx.x * blockDim.x + threadIdx.x) >> 5;
    int lane  = threadIdx.x & 31;
    int wslot = (threadIdx.x >> 5) & 7;
    if (wg >= ROWS) return;

    unsigned long long v = g_p12[(size_t)wg * NT + lane];
    unsigned t1 = (unsigned)(v >> 32), t2 = (unsigned)v;

    unsigned M1 = wmax32(t1);
    float lim = dec_key(M1) - (2.f * __uint_as_float((unsigned)g_bbits) + 0.03f);

    bool q1 = dec_key(t1) >= lim;
    bool q2 = dec_key(t2) >= lim;
    unsigned b1 = __ballot_sync(0xffffffffu, q1);
    unsigned b2 = __ballot_sync(0xffffffffu, q2);
    int n1 = __popc(b1);
    unsigned lm = (1u << lane) - 1u;
    if (q1) cands[wslot][__popc(b1 & lm)]      = (unsigned short)(lane * 64 + 63 - (int)(t1 & 0x3Fu));
    if (q2) cands[wslot][n1 + __popc(b2 & lm)] = (unsigned short)(lane * 64 + 63 - (int)(t2 & 0x3Fu));
    int nc = n1 + __popc(b2);
    __syncwarp();

    unsigned long long mask = g_mask[wg];
    unsigned long long best = 0;
    for (int k = lane; k < 2 * nc; k += 32) {    // one COLUMN per lane
        int col = (int)cands[wslot][k >> 1] * 2 + (k & 1);
        const __half* hr = g_Hh + (size_t)col * 96;
        float s = 0.f;
#pragma unroll
        for (int d = 0; d < 45; d++) {
            float sgn = ((mask >> d) & 1ull) ? -1.f : 1.f;
            s += sgn * (__half2float(hr[d]) + __half2float(hr[48 + d]));
        }
        unsigned long long pk = ((unsigned long long)pack_key(s) << 32)
                              | (unsigned long long)(4095u - (unsigned)col);
        if (pk > best) best = pk;
    }
    best = wmax64(best);
    if (lane == 0) {
        int col = 4095 - (int)(unsigned)best;
        int g   = wg % 10;
        const float2* l2 = reinterpret_cast<const float2*>(LUT);
        out[wg] = l2[(size_t)g * NCOLS + col];
    }
}

// ---------------------------------------------------------------------------
extern "C" void kernel_launch(void* const* d_in, const int* in_sizes, int n_in,
                              void* d_out, int out_size)
{
    const float* x   = (const float*)d_in[0];
    const float* S   = (const float*)d_in[1];
    const float* T   = (const float*)d_in[2];
    const float* H   = (const float*)d_in[3];
    const float* LUT = (const float*)d_in[4];
    (void)in_sizes; (void)n_in; (void)out_size;

    cudaFuncSetAttribute(k_gemm, cudaFuncAttributeMaxDynamicSharedMemorySize, SM_TOT);

    k_prep <<<336, 256>>>(x, S, T, H);
    k_gemm <<<MSLOTS * NT, 256, SM_TOT>>>();
    k_merge<<<(ROWS * 32 + 255) / 256, 256>>>(LUT, (float2*)d_out);
}